// round 16
// baseline (speedup 1.0000x reference)
#include <cuda_runtime.h>

#define RR 256
#define BB 32
#define TT 32
#define YSZ 64

// Scratch for the stage-1 result x[b, p, q] (B,256,256) fp32 = 8.4 MB.
__device__ float g_x[BB * RR * RR];

// ---------------- f32x2 helpers (sm_100+ packed fp32) ----------------
typedef unsigned long long u64t;
__device__ __forceinline__ u64t pk2(float lo, float hi) {
  u64t r; asm("mov.b64 %0, {%1, %2};" : "=l"(r) : "f"(lo), "f"(hi)); return r;
}
__device__ __forceinline__ void fma2(u64t& d, u64t a, u64t b) {
  asm("fma.rn.f32x2 %0, %1, %2, %0;" : "+l"(d) : "l"(a), "l"(b));
}
__device__ __forceinline__ float2 upk2(u64t v) {
  float2 f; asm("mov.b64 {%0, %1}, %2;" : "=f"(f.x), "=f"(f.y) : "l"(v)); return f;
}

// ---------------------------------------------------------------------------
// Stage 1: x[b,p,q] = sum_t Ht[t,p,q] * yt[b,t,p>>2,q>>2]
// ---------------------------------------------------------------------------
__global__ __launch_bounds__(256) void stage1_kernel(
    const float* __restrict__ yt, const float* __restrict__ Ht) {
  int tx = threadIdx.x;                     // 0..63  -> q4
  int p  = blockIdx.x * 4 + threadIdx.y;    // 0..255
  int bg = blockIdx.y;                      // 0..3 (8 batches each)
  int q0 = tx * 4;
  int p4 = p >> 2;

  float acc[8][4];
#pragma unroll
  for (int i = 0; i < 8; i++)
#pragma unroll
    for (int j = 0; j < 4; j++) acc[i][j] = 0.f;

#pragma unroll 4
  for (int t = 0; t < TT; t++) {
    float4 h = *reinterpret_cast<const float4*>(Ht + ((size_t)t * RR + p) * RR + q0);
    const float* yb = yt + ((size_t)(bg * 8) * TT + t) * (YSZ * YSZ) + p4 * YSZ + tx;
#pragma unroll
    for (int bi = 0; bi < 8; bi++) {
      float yv = yb[(size_t)bi * TT * YSZ * YSZ];
      acc[bi][0] = fmaf(h.x, yv, acc[bi][0]);
      acc[bi][1] = fmaf(h.y, yv, acc[bi][1]);
      acc[bi][2] = fmaf(h.z, yv, acc[bi][2]);
      acc[bi][3] = fmaf(h.w, yv, acc[bi][3]);
    }
  }
#pragma unroll
  for (int bi = 0; bi < 8; bi++) {
    float4 o = make_float4(acc[bi][0], acc[bi][1], acc[bi][2], acc[bi][3]);
    *reinterpret_cast<float4*>(g_x + ((size_t)(bg * 8 + bi) * RR + p) * RR + q0) = o;
  }
}

// ---------------------------------------------------------------------------
// Stage 2: fused conv(1->32,3x3) -> ReLU -> conv(32->1,3x3), SAME padding.
// One block = one batch x one 64x32 output tile. 256 threads, 8 px/thread
// (2 rows x 4 cols). Channels in 16 groups of 2 (keeps smem < 48KB static,
// no dynamic-smem opt-in, no host-side attribute calls).
// conv1: f32x2 packs the two output rows of each 2x4 unit; vertical input
//        pairs shared across channels; relu1 staged in smem via STS.128.
// conv2: scalar FFMA, 4-row vectorized smem reads (8 px amortization).
// ---------------------------------------------------------------------------
__global__ __launch_bounds__(256) void conv_kernel(
    const float* __restrict__ W1, const float* __restrict__ b1,
    const float* __restrict__ W2, const float* __restrict__ b2,
    float* __restrict__ out) {
  __shared__ __align__(16) float  rs[2][66][36];   // relu1, 2-ch group (18.6KB)
  __shared__ __align__(16) float  xs[68][40];      // x tile + 2-halo (10.6KB)
  __shared__ __align__(16) float2 w1p[288];        // conv1 weights dup (w,w)
  __shared__ float b1s[32];

  int tid = threadIdx.x;
  int bb  = blockIdx.z;
  int oy0 = blockIdx.y * 64, ox0 = blockIdx.x * 32;
  bool edge = (blockIdx.x == 0) | (blockIdx.x == 7) |
              (blockIdx.y == 0) | (blockIdx.y == 3);
  const float* xb = g_x + (size_t)bb * RR * RR;

  for (int i = tid; i < 288; i += 256) {
    float w = W1[i];
    w1p[i] = make_float2(w, w);
  }
  if (tid < 32) b1s[tid] = b1[tid];

  // Load x tile rows oy0-2..oy0+65, cols ox0-2..ox0+35 (cols 38,39 unused)
  if (edge) {
    for (int i = tid; i < 68 * 38; i += 256) {
      int r = i / 38, c = i - r * 38;
      int gy = oy0 - 2 + r, gx = ox0 - 2 + c;
      float v = 0.f;
      if ((unsigned)gy < 256u && (unsigned)gx < 256u) v = xb[gy * 256 + gx];
      xs[r][c] = v;
    }
  } else {
    for (int i = tid; i < 68 * 38; i += 256) {
      int r = i / 38, c = i - r * 38;
      xs[r][c] = xb[(oy0 - 2 + r) * 256 + (ox0 - 2 + c)];
    }
  }
  __syncthreads();

  float bias2 = __ldg(b2);
  int oly  = (tid >> 3) * 2;    // output row base in tile (0..62, step 2)
  int olx0 = (tid & 7) * 4;     // output col base (0..28)
  float acc[2][4];
#pragma unroll
  for (int r = 0; r < 2; r++)
#pragma unroll
    for (int j = 0; j < 4; j++) acc[r][j] = bias2;

  for (int cg = 0; cg < 16; cg++) {
    if (cg) __syncthreads();  // previous group's conv2 reads must finish

    // ---- conv1 + ReLU over rs rows 0..65 in 2-row x 4-col units ----
    for (int i = tid; i < 33 * 9; i += 256) {
      int ur = i / 9, uq = i - ur * 9;
      int ry0 = ur * 2, c0 = uq * 4;

      float v[4][6];
#pragma unroll
      for (int r = 0; r < 4; r++) {
        const float* xr = &xs[ry0 + r][c0];
        float4 a   = *reinterpret_cast<const float4*>(xr);
        float2 b2v = *reinterpret_cast<const float2*>(xr + 4);
        v[r][0] = a.x; v[r][1] = a.y; v[r][2] = a.z;
        v[r][3] = a.w; v[r][4] = b2v.x; v[r][5] = b2v.y;
      }
      // vertical pairs shared across both channels of the group
      u64t P[3][6];
#pragma unroll
      for (int r = 0; r < 3; r++)
#pragma unroll
        for (int k = 0; k < 6; k++) P[r][k] = pk2(v[r][k], v[r + 1][k]);

      bool rAok = true, rBok = true;
      bool cok0 = true, cok1 = true, cok2 = true, cok3 = true;
      if (edge) {
        int gyA = oy0 + ry0 - 1;
        rAok = (unsigned)gyA < 256u;
        rBok = (unsigned)(gyA + 1) < 256u;
        int gx = ox0 + c0 - 1;
        cok0 = (unsigned)gx < 256u;
        cok1 = (unsigned)(gx + 1) < 256u;
        cok2 = (unsigned)(gx + 2) < 256u;
        cok3 = (unsigned)(gx + 3) < 256u;
      }

#pragma unroll
      for (int cl = 0; cl < 2; cl++) {
        int ch = cg * 2 + cl;
        u64t w[9];
#pragma unroll
        for (int t = 0; t < 9; t++)
          w[t] = *reinterpret_cast<const u64t*>(&w1p[ch * 9 + t]);
        float bv = b1s[ch];
        u64t a0 = pk2(bv, bv), a1 = a0, a2 = a0, a3 = a0;
#pragma unroll
        for (int dy = 0; dy < 3; dy++)
#pragma unroll
          for (int dx = 0; dx < 3; dx++) {
            u64t wt = w[dy * 3 + dx];
            fma2(a0, wt, P[dy][dx]);
            fma2(a1, wt, P[dy][dx + 1]);
            fma2(a2, wt, P[dy][dx + 2]);
            fma2(a3, wt, P[dy][dx + 3]);
          }
        float2 f0 = upk2(a0), f1 = upk2(a1), f2 = upk2(a2), f3 = upk2(a3);
        float s00 = fmaxf(f0.x, 0.f), s01 = fmaxf(f1.x, 0.f),
              s02 = fmaxf(f2.x, 0.f), s03 = fmaxf(f3.x, 0.f);
        float s10 = fmaxf(f0.y, 0.f), s11 = fmaxf(f1.y, 0.f),
              s12 = fmaxf(f2.y, 0.f), s13 = fmaxf(f3.y, 0.f);
        if (edge) {
          s00 = (rAok && cok0) ? s00 : 0.f; s01 = (rAok && cok1) ? s01 : 0.f;
          s02 = (rAok && cok2) ? s02 : 0.f; s03 = (rAok && cok3) ? s03 : 0.f;
          s10 = (rBok && cok0) ? s10 : 0.f; s11 = (rBok && cok1) ? s11 : 0.f;
          s12 = (rBok && cok2) ? s12 : 0.f; s13 = (rBok && cok3) ? s13 : 0.f;
        }
        *reinterpret_cast<float4*>(&rs[cl][ry0][c0]) =
            make_float4(s00, s01, s02, s03);
        *reinterpret_cast<float4*>(&rs[cl][ry0 + 1][c0]) =
            make_float4(s10, s11, s12, s13);
      }
    }
    __syncthreads();

    // ---- conv2 partial accumulation for this channel group ----
    const float* W2g = W2 + cg * 2 * 9;
#pragma unroll
    for (int cl = 0; cl < 2; cl++) {
      float w2r[9];
#pragma unroll
      for (int t = 0; t < 9; t++) w2r[t] = __ldg(&W2g[cl * 9 + t]);

      float v[4][6];
#pragma unroll
      for (int r = 0; r < 4; r++) {
        const float* rr = &rs[cl][oly + r][olx0];
        float4 a   = *reinterpret_cast<const float4*>(rr);
        float2 b2v = *reinterpret_cast<const float2*>(rr + 4);
        v[r][0] = a.x; v[r][1] = a.y; v[r][2] = a.z;
        v[r][3] = a.w; v[r][4] = b2v.x; v[r][5] = b2v.y;
      }
#pragma unroll
      for (int r2 = 0; r2 < 2; r2++)
#pragma unroll
        for (int dy = 0; dy < 3; dy++) {
          float w0 = w2r[dy * 3], w1v = w2r[dy * 3 + 1], w2v = w2r[dy * 3 + 2];
          const float* vv = v[r2 + dy];
          acc[r2][0] = fmaf(w0, vv[0], acc[r2][0]);
          acc[r2][0] = fmaf(w1v, vv[1], acc[r2][0]);
          acc[r2][0] = fmaf(w2v, vv[2], acc[r2][0]);
          acc[r2][1] = fmaf(w0, vv[1], acc[r2][1]);
          acc[r2][1] = fmaf(w1v, vv[2], acc[r2][1]);
          acc[r2][1] = fmaf(w2v, vv[3], acc[r2][1]);
          acc[r2][2] = fmaf(w0, vv[2], acc[r2][2]);
          acc[r2][2] = fmaf(w1v, vv[3], acc[r2][2]);
          acc[r2][2] = fmaf(w2v, vv[4], acc[r2][2]);
          acc[r2][3] = fmaf(w0, vv[3], acc[r2][3]);
          acc[r2][3] = fmaf(w1v, vv[4], acc[r2][3]);
          acc[r2][3] = fmaf(w2v, vv[5], acc[r2][3]);
        }
    }
  }

#pragma unroll
  for (int r2 = 0; r2 < 2; r2++) {
    float4 o = make_float4(acc[r2][0], acc[r2][1], acc[r2][2], acc[r2][3]);
    *reinterpret_cast<float4*>(
        out + ((size_t)bb * RR + oy0 + oly + r2) * RR + ox0 + olx0) = o;
  }
}

extern "C" void kernel_launch(void* const* d_in, const int* in_sizes, int n_in,
                              void* d_out, int out_size) {
  const float* yt = (const float*)d_in[0];
  const float* Ht = (const float*)d_in[1];
  const float* W1 = (const float*)d_in[2];
  const float* b1 = (const float*)d_in[3];
  const float* W2 = (const float*)d_in[4];
  const float* b2 = (const float*)d_in[5];
  float* out = (float*)d_out;

  stage1_kernel<<<dim3(64, 4), dim3(64, 4)>>>(yt, Ht);
  conv_kernel<<<dim3(8, 4, 32), 256>>>(W1, b1, W2, b2, out);
}

// round 17
// speedup vs baseline: 1.5199x; 1.5199x over previous
#include <cuda_runtime.h>

#define RR 256
#define BB 32
#define TT 32
#define YSZ 64

// Scratch for the stage-1 result x[b, p, q] (B,256,256) fp32 = 8.4 MB.
__device__ float g_x[BB * RR * RR];

// ---------------------------------------------------------------------------
// Stage 1: x[b,p,q] = sum_t Ht[t,p,q] * yt[b,t,p>>2,q>>2]   (unchanged, ~5us)
// ---------------------------------------------------------------------------
__global__ __launch_bounds__(256) void stage1_kernel(
    const float* __restrict__ yt, const float* __restrict__ Ht) {
  int tx = threadIdx.x;                     // 0..63  -> q4
  int p  = blockIdx.x * 4 + threadIdx.y;    // 0..255
  int bg = blockIdx.y;                      // 0..3 (8 batches each)
  int q0 = tx * 4;
  int p4 = p >> 2;

  float acc[8][4];
#pragma unroll
  for (int i = 0; i < 8; i++)
#pragma unroll
    for (int j = 0; j < 4; j++) acc[i][j] = 0.f;

#pragma unroll 4
  for (int t = 0; t < TT; t++) {
    float4 h = *reinterpret_cast<const float4*>(Ht + ((size_t)t * RR + p) * RR + q0);
    const float* yb = yt + ((size_t)(bg * 8) * TT + t) * (YSZ * YSZ) + p4 * YSZ + tx;
#pragma unroll
    for (int bi = 0; bi < 8; bi++) {
      float yv = yb[(size_t)bi * TT * YSZ * YSZ];
      acc[bi][0] = fmaf(h.x, yv, acc[bi][0]);
      acc[bi][1] = fmaf(h.y, yv, acc[bi][1]);
      acc[bi][2] = fmaf(h.z, yv, acc[bi][2]);
      acc[bi][3] = fmaf(h.w, yv, acc[bi][3]);
    }
  }
#pragma unroll
  for (int bi = 0; bi < 8; bi++) {
    float4 o = make_float4(acc[bi][0], acc[bi][1], acc[bi][2], acc[bi][3]);
    *reinterpret_cast<float4*>(g_x + ((size_t)(bg * 8 + bi) * RR + p) * RR + q0) = o;
  }
}

// ---------------------------------------------------------------------------
// Stage 2: fused conv(1->32,3x3) -> ReLU -> conv(32->1,3x3), SAME padding.
// One block = one batch x one 32x32 output tile, 128 threads, 8 px/thread
// (2 rows x 4 cols). Channels in 8 groups of 4. ALL SCALAR FFMA (no f32x2 —
// R16 showed register-pair marshalling moves the cost to the ALU pipe).
// conv1: 2-row x 4-col units — input rows loaded once feed 2 output rows and
//        all 4 channels of the group; relu1 stored with STS.128.
// conv2: 2x4 px/thread, 4-row vectorized reads amortized over 8 px.
// Static smem ~26.6KB -> no opt-in, no host attribute calls.
// ---------------------------------------------------------------------------
__global__ __launch_bounds__(128) void conv_kernel(
    const float* __restrict__ W1, const float* __restrict__ b1,
    const float* __restrict__ W2, const float* __restrict__ b2,
    float* __restrict__ out) {
  __shared__ __align__(16) float rs[4][34][36];  // relu1, 4-ch group (19.6KB)
  __shared__ __align__(16) float xs[36][40];     // x tile + 2-halo (5.8KB)
  __shared__ float w1s[288], b1s[32];

  int tid = threadIdx.x;
  int bb  = blockIdx.z;
  int oy0 = blockIdx.y * 32, ox0 = blockIdx.x * 32;
  bool edge = (blockIdx.x == 0) | (blockIdx.x == 7) |
              (blockIdx.y == 0) | (blockIdx.y == 7);
  const float* xb = g_x + (size_t)bb * RR * RR;

  for (int i = tid; i < 288; i += 128) w1s[i] = W1[i];
  if (tid < 32) b1s[tid] = b1[tid];

  // Load x tile rows oy0-2..oy0+33, cols ox0-2..ox0+35 (38 cols used of 40)
  if (edge) {
    for (int i = tid; i < 36 * 38; i += 128) {
      int r = i / 38, c = i - r * 38;
      int gy = oy0 - 2 + r, gx = ox0 - 2 + c;
      float v = 0.f;
      if ((unsigned)gy < 256u && (unsigned)gx < 256u) v = xb[gy * 256 + gx];
      xs[r][c] = v;
    }
  } else {
    for (int i = tid; i < 36 * 38; i += 128) {
      int r = i / 38, c = i - r * 38;
      xs[r][c] = xb[(oy0 - 2 + r) * 256 + (ox0 - 2 + c)];
    }
  }
  __syncthreads();

  float bias2 = __ldg(b2);
  int oly  = (tid >> 3) * 2;    // output row base 0..30 (step 2)
  int olx0 = (tid & 7) * 4;     // output col base 0..28
  float acc[2][4];
#pragma unroll
  for (int r = 0; r < 2; r++)
#pragma unroll
    for (int j = 0; j < 4; j++) acc[r][j] = bias2;

  for (int cg = 0; cg < 8; cg++) {
    if (cg) __syncthreads();  // previous group's conv2 reads of rs must finish

    // ---- conv1 + ReLU: rs rows 0..33 in 2-row x 4-col units (17x9 tasks) --
    for (int i = tid; i < 17 * 9; i += 128) {
      int ur = i / 9, uq = i - ur * 9;
      int ry0 = ur * 2, c0 = uq * 4;

      float v[4][6];
#pragma unroll
      for (int r = 0; r < 4; r++) {
        const float* xr = &xs[ry0 + r][c0];
        float4 a   = *reinterpret_cast<const float4*>(xr);
        float2 bv  = *reinterpret_cast<const float2*>(xr + 4);
        v[r][0] = a.x; v[r][1] = a.y; v[r][2] = a.z;
        v[r][3] = a.w; v[r][4] = bv.x; v[r][5] = bv.y;
      }

      bool rok[2] = {true, true};
      bool cok[4] = {true, true, true, true};
      if (edge) {
        int gy = oy0 + ry0 - 1;
        rok[0] = (unsigned)gy < 256u;
        rok[1] = (unsigned)(gy + 1) < 256u;
        int gx = ox0 + c0 - 1;
#pragma unroll
        for (int j = 0; j < 4; j++) cok[j] = (unsigned)(gx + j) < 256u;
      }

#pragma unroll
      for (int cl = 0; cl < 4; cl++) {
        int ch = cg * 4 + cl;
        float w1r[9];
#pragma unroll
        for (int t = 0; t < 9; t++) w1r[t] = w1s[ch * 9 + t];
        float bv = b1s[ch];

#pragma unroll
        for (int rr = 0; rr < 2; rr++) {
          float s0 = bv, s1 = bv, s2 = bv, s3 = bv;
#pragma unroll
          for (int dy = 0; dy < 3; dy++) {
            float wa = w1r[dy * 3], wb = w1r[dy * 3 + 1], wc = w1r[dy * 3 + 2];
            const float* vv = v[rr + dy];
            s0 = fmaf(wa, vv[0], s0); s0 = fmaf(wb, vv[1], s0); s0 = fmaf(wc, vv[2], s0);
            s1 = fmaf(wa, vv[1], s1); s1 = fmaf(wb, vv[2], s1); s1 = fmaf(wc, vv[3], s1);
            s2 = fmaf(wa, vv[2], s2); s2 = fmaf(wb, vv[3], s2); s2 = fmaf(wc, vv[4], s2);
            s3 = fmaf(wa, vv[3], s3); s3 = fmaf(wb, vv[4], s3); s3 = fmaf(wc, vv[5], s3);
          }
          s0 = fmaxf(s0, 0.f); s1 = fmaxf(s1, 0.f);
          s2 = fmaxf(s2, 0.f); s3 = fmaxf(s3, 0.f);
          if (edge) {
            s0 = (rok[rr] && cok[0]) ? s0 : 0.f;
            s1 = (rok[rr] && cok[1]) ? s1 : 0.f;
            s2 = (rok[rr] && cok[2]) ? s2 : 0.f;
            s3 = (rok[rr] && cok[3]) ? s3 : 0.f;
          }
          *reinterpret_cast<float4*>(&rs[cl][ry0 + rr][c0]) =
              make_float4(s0, s1, s2, s3);
        }
      }
    }
    __syncthreads();

    // ---- conv2 partial accumulation for this channel group ----
    const float* W2g = W2 + cg * 4 * 9;
#pragma unroll
    for (int cl = 0; cl < 4; cl++) {
      float w2r[9];
#pragma unroll
      for (int t = 0; t < 9; t++) w2r[t] = __ldg(&W2g[cl * 9 + t]);

      float v[4][6];
#pragma unroll
      for (int r = 0; r < 4; r++) {
        const float* rr = &rs[cl][oly + r][olx0];
        float4 a  = *reinterpret_cast<const float4*>(rr);
        float2 bv = *reinterpret_cast<const float2*>(rr + 4);
        v[r][0] = a.x; v[r][1] = a.y; v[r][2] = a.z;
        v[r][3] = a.w; v[r][4] = bv.x; v[r][5] = bv.y;
      }
#pragma unroll
      for (int r2 = 0; r2 < 2; r2++)
#pragma unroll
        for (int dy = 0; dy < 3; dy++) {
          float wa = w2r[dy * 3], wb = w2r[dy * 3 + 1], wc = w2r[dy * 3 + 2];
          const float* vv = v[r2 + dy];
          acc[r2][0] = fmaf(wa, vv[0], acc[r2][0]);
          acc[r2][0] = fmaf(wb, vv[1], acc[r2][0]);
          acc[r2][0] = fmaf(wc, vv[2], acc[r2][0]);
          acc[r2][1] = fmaf(wa, vv[1], acc[r2][1]);
          acc[r2][1] = fmaf(wb, vv[2], acc[r2][1]);
          acc[r2][1] = fmaf(wc, vv[3], acc[r2][1]);
          acc[r2][2] = fmaf(wa, vv[2], acc[r2][2]);
          acc[r2][2] = fmaf(wb, vv[3], acc[r2][2]);
          acc[r2][2] = fmaf(wc, vv[4], acc[r2][2]);
          acc[r2][3] = fmaf(wa, vv[3], acc[r2][3]);
          acc[r2][3] = fmaf(wb, vv[4], acc[r2][3]);
          acc[r2][3] = fmaf(wc, vv[5], acc[r2][3]);
        }
    }
  }

#pragma unroll
  for (int r2 = 0; r2 < 2; r2++) {
    float4 o = make_float4(acc[r2][0], acc[r2][1], acc[r2][2], acc[r2][3]);
    *reinterpret_cast<float4*>(
        out + ((size_t)bb * RR + oy0 + oly + r2) * RR + ox0 + olx0) = o;
  }
}

extern "C" void kernel_launch(void* const* d_in, const int* in_sizes, int n_in,
                              void* d_out, int out_size) {
  const float* yt = (const float*)d_in[0];
  const float* Ht = (const float*)d_in[1];
  const float* W1 = (const float*)d_in[2];
  const float* b1 = (const float*)d_in[3];
  const float* W2 = (const float*)d_in[4];
  const float* b2 = (const float*)d_in[5];
  float* out = (float*)d_out;

  stage1_kernel<<<dim3(64, 4), dim3(64, 4)>>>(yt, Ht);
  conv_kernel<<<dim3(8, 8, 32), 128>>>(W1, b1, W2, b2, out);
}